// round 15
// baseline (speedup 1.0000x reference)
#include <cuda_runtime.h>

#define N_NODES 100000
#define G_NODES 50000
#define NE      800000
#define H       64
#define FIN     32
#define NG      128
#define TILE    96
#define MAXT    1064
#define LN_EPS  1e-5f

// ---------------- device scratch (allowed: __device__ globals) ----------------
__device__ float g_h[(size_t)N_NODES * H];
__device__ float g_h0[(size_t)N_NODES * H];
__device__ float g_hsum[(size_t)N_NODES * H];
__device__ int   g_deg[N_NODES];
__device__ int   g_rowstart[N_NODES];
__device__ int   g_cursor[N_NODES];
__device__ int   g_csr_src[NE];
__device__ int   g_alloc;
__device__ int   g_bcnt[21];
__device__ int   g_bcur[21];
__device__ int   g_boff[22];
__device__ int   g_toff[22];
__device__ int   g_sorted[N_NODES];
__device__ float g_pooled[NG * H];

// ---------------- helpers ----------------
__device__ __forceinline__ unsigned long long fma2(unsigned long long a,
                                                   unsigned long long b,
                                                   unsigned long long c) {
    unsigned long long d;
    asm("fma.rn.f32x2 %0, %1, %2, %3;" : "=l"(d) : "l"(a), "l"(b), "l"(c));
    return d;
}

__device__ __forceinline__ unsigned long long pack2(float v) {
    union { float2 f; unsigned long long u; } p;
    p.f.x = v; p.f.y = v;
    return p.u;
}

// ---------------- embedding: h = x @ emb_w + emb_b ; h0 = h ----------------
__global__ void embed_k(const float* __restrict__ x,
                        const float* __restrict__ w,
                        const float* __restrict__ b) {
    __shared__ float sw[FIN * H];
    __shared__ float sb[H];
    for (int i = threadIdx.x; i < FIN * H; i += blockDim.x) sw[i] = w[i];
    if (threadIdx.x < H) sb[threadIdx.x] = b[threadIdx.x];
    __syncthreads();
    int t = blockIdx.x * blockDim.x + threadIdx.x;  // over N*32
    if (t >= N_NODES * 32) return;
    int node = t >> 5, c = t & 31;
    const float* xr = x + node * FIN;
    float a0 = sb[c], a1 = sb[c + 32];
#pragma unroll
    for (int f = 0; f < FIN; f++) {
        float xv = xr[f];
        a0 = fmaf(xv, sw[f * H + c], a0);
        a1 = fmaf(xv, sw[f * H + c + 32], a1);
    }
    size_t base = (size_t)node * H;
    g_h[base + c] = a0;  g_h[base + c + 32] = a1;
    g_h0[base + c] = a0; g_h0[base + c + 32] = a1;
}

// ---------------- per-conv CSR / bucket build ----------------
__global__ void reset_k() {
    int t = blockIdx.x * blockDim.x + threadIdx.x;
    if (t < N_NODES) g_deg[t] = 0;
    if (t == 0) g_alloc = 0;
    if (t < 21) { g_bcnt[t] = 0; g_bcur[t] = 0; }
}

__global__ void hist_k(const int* __restrict__ ei) {
    int e = blockIdx.x * blockDim.x + threadIdx.x;
    if (e < NE) atomicAdd(&g_deg[ei[NE + e]], 1);
}

__global__ void alloc_k() {
    int i = blockIdx.x * blockDim.x + threadIdx.x;
    if (i >= N_NODES) return;
    int d = g_deg[i];
    int st = atomicAdd(&g_alloc, d);
    g_rowstart[i] = st;
    g_cursor[i]   = st;
    int bkt = d < 20 ? d : 20;
    atomicAdd(&g_bcnt[bkt], 1);
}

__global__ void fill_k(const int* __restrict__ ei) {
    int e = blockIdx.x * blockDim.x + threadIdx.x;
    if (e >= NE) return;
    int dst = ei[NE + e];
    int pos = atomicAdd(&g_cursor[dst], 1);
    g_csr_src[pos] = ei[e];
}

__global__ void boff_k() {
    if (threadIdx.x == 0 && blockIdx.x == 0) {
        int off = 0, t = 0;
        for (int q = 0; q < 21; q++) {
            g_boff[q] = off; g_toff[q] = t;
            int c = g_bcnt[q];
            off += c;
            t += (c + TILE - 1) / TILE;
        }
        g_boff[21] = off; g_toff[21] = t;
    }
}

__global__ void bscatter_k() {
    int i = blockIdx.x * blockDim.x + threadIdx.x;
    if (i >= N_NODES) return;
    int d = g_deg[i];
    int bkt = d < 20 ? d : 20;
    int pos = g_boff[bkt] + atomicAdd(&g_bcur[bkt], 1);
    g_sorted[pos] = i;
}

// ---------------- aggregation: hsum[i] = sum_{e: dst==i} h[src_e] ----------------
__global__ void aggregate_k() {
    int gt = blockIdx.x * blockDim.x + threadIdx.x;   // N*32 threads, warp per node
    int node = gt >> 5;
    if (node >= N_NODES) return;
    int lane = gt & 31;
    int start = g_rowstart[node];
    int d = g_deg[node];
    const float2* hp = (const float2*)g_h;
    float2 acc = make_float2(0.f, 0.f);
    int e = 0;
    for (; e + 4 <= d; e += 4) {
        int s0 = g_csr_src[start + e];
        int s1 = g_csr_src[start + e + 1];
        int s2 = g_csr_src[start + e + 2];
        int s3 = g_csr_src[start + e + 3];
        float2 v0 = hp[(size_t)s0 * 32 + lane];
        float2 v1 = hp[(size_t)s1 * 32 + lane];
        float2 v2 = hp[(size_t)s2 * 32 + lane];
        float2 v3 = hp[(size_t)s3 * 32 + lane];
        acc.x += v0.x + v1.x + v2.x + v3.x;
        acc.y += v0.y + v1.y + v2.y + v3.y;
    }
    for (; e < d; e++) {
        int s = g_csr_src[start + e];
        float2 v = hp[(size_t)s * 32 + lane];
        acc.x += v.x; acc.y += v.y;
    }
    ((float2*)g_hsum)[(size_t)node * 32 + lane] = acc;
}

// ---------------- bucketed linear: h = [relu](hsum@wl[k] + bl[k] + h@wr[k]) ----------------
__device__ __forceinline__ void stage_rows(const float* __restrict__ base,
                                           int node, int lane, int warp,
                                           float* __restrict__ s_row) {
#pragma unroll 1
    for (int r = 0; r < 32; r++) {
        int nd = __shfl_sync(0xffffffffu, node, r);
        float2 v = ((const float2*)(base + (size_t)nd * H))[lane];
        int row = warp * 32 + r;
        s_row[row * 65 + 2 * lane]     = v.x;
        s_row[row * 65 + 2 * lane + 1] = v.y;
    }
    __syncwarp();
}

__device__ __forceinline__ void compute_phase(const float* __restrict__ s_w,
                                              const float* __restrict__ myrow,
                                              unsigned long long* acc) {
#pragma unroll 4
    for (int f = 0; f < H; f++) {
        unsigned long long ss = pack2(myrow[f]);
        const ulonglong2* wf = (const ulonglong2*)(s_w + f * H);
#pragma unroll
        for (int q = 0; q < 16; q++) {
            ulonglong2 wv = wf[q];
            acc[2 * q]     = fma2(ss, wv.x, acc[2 * q]);
            acc[2 * q + 1] = fma2(ss, wv.y, acc[2 * q + 1]);
        }
    }
}

__global__ __launch_bounds__(TILE) void transform_k(const float* __restrict__ wl_all,
                                                    const float* __restrict__ bl_all,
                                                    const float* __restrict__ wr_all,
                                                    int jconv, int do_relu) {
    __shared__ float s_w[H * H];       // 16 KB, reused for wl then wr
    __shared__ float s_bl[H];
    __shared__ float s_row[TILE * 65]; // padded rows
    __shared__ int s_meta[3];

    int tid = threadIdx.x;
    if (tid == 0) {
        int t = blockIdx.x;
        int k = -1, pos0 = 0, cnt = 0;
        int total = g_toff[21];
        if (t < total) {
#pragma unroll 1
            for (int q = 0; q < 21; q++) {
                if (t < g_toff[q + 1]) { k = q; break; }
            }
            pos0 = g_boff[k] + (t - g_toff[k]) * TILE;
            int rem = g_boff[k + 1] - pos0;
            cnt = rem < TILE ? rem : TILE;
        }
        s_meta[0] = k; s_meta[1] = pos0; s_meta[2] = cnt;
    }
    __syncthreads();
    int k = s_meta[0];
    if (k < 0) return;                       // block-uniform
    int pos0 = s_meta[1], cnt = s_meta[2];
    int ii = tid < cnt ? tid : cnt - 1;      // clamp for full-warp participation
    int node = g_sorted[pos0 + ii];

    if (k == 0) {                            // deg==0: passthrough (+relu for j<3)
        if (do_relu && tid < cnt) {
            float4* hp = (float4*)(g_h + (size_t)node * H);
#pragma unroll
            for (int q = 0; q < 16; q++) {
                float4 v = hp[q];
                v.x = fmaxf(v.x, 0.f); v.y = fmaxf(v.y, 0.f);
                v.z = fmaxf(v.z, 0.f); v.w = fmaxf(v.w, 0.f);
                hp[q] = v;
            }
        }
        return;                              // block-uniform
    }

    const float* wl = wl_all + (size_t)(jconv * 21 + k) * H * H;
    const float* wr = wr_all + (size_t)(jconv * 21 + k) * H * H;
    const float* bl = bl_all + (size_t)(jconv * 21 + k) * H;

    // load wl + bias
    {
        const float4* src = (const float4*)wl;
        float4* dst4 = (float4*)s_w;
        for (int i = tid; i < H * H / 4; i += TILE) dst4[i] = src[i];
        if (tid < H) s_bl[tid] = bl[tid];
    }
    __syncthreads();

    int lane = tid & 31, warp = tid >> 5;
    unsigned long long acc[32];
#pragma unroll
    for (int p = 0; p < 32; p++) acc[p] = ((const unsigned long long*)s_bl)[p];

    stage_rows(g_hsum, node, lane, warp, s_row);
    compute_phase(s_w, s_row + tid * 65, acc);

    __syncthreads();   // everyone done with wl
    {
        const float4* src = (const float4*)wr;
        float4* dst4 = (float4*)s_w;
        for (int i = tid; i < H * H / 4; i += TILE) dst4[i] = src[i];
    }
    __syncthreads();

    stage_rows(g_h, node, lane, warp, s_row);
    compute_phase(s_w, s_row + tid * 65, acc);

    if (tid < cnt) {
        float2* outp = (float2*)(g_h + (size_t)node * H);
#pragma unroll
        for (int p = 0; p < 32; p++) {
            float2 v = *(float2*)&acc[p];
            if (do_relu) { v.x = fmaxf(v.x, 0.f); v.y = fmaxf(v.y, 0.f); }
            outp[p] = v;
        }
    }
}

// ---------------- layernorm + residual ----------------
__global__ void ln_k(const float* __restrict__ gamma, const float* __restrict__ beta) {
    int gt = blockIdx.x * blockDim.x + threadIdx.x;   // warp per node
    int node = gt >> 5;
    if (node >= N_NODES) return;
    int lane = gt & 31;
    float2* hp = (float2*)(g_h + (size_t)node * H);
    float2 v = hp[lane];
    float s = v.x + v.y;
#pragma unroll
    for (int o = 16; o > 0; o >>= 1) s += __shfl_xor_sync(0xffffffffu, s, o);
    float mu = s * (1.f / H);
    float dx = v.x - mu, dy = v.y - mu;
    float q = dx * dx + dy * dy;
#pragma unroll
    for (int o = 16; o > 0; o >>= 1) q += __shfl_xor_sync(0xffffffffu, q, o);
    float rs = rsqrtf(q * (1.f / H) + LN_EPS);
    float2 h0v = ((const float2*)(g_h0 + (size_t)node * H))[lane];
    float gx = gamma[2 * lane], gy = gamma[2 * lane + 1];
    float bx = beta[2 * lane],  by = beta[2 * lane + 1];
    float2 o2;
    o2.x = dx * rs * gx + bx + h0v.x;
    o2.y = dy * rs * gy + by + h0v.y;
    hp[lane] = o2;
}

// ---------------- pooling + output ----------------
__global__ void zero_pooled_k() {
    int t = blockIdx.x * blockDim.x + threadIdx.x;
    if (t < NG * H) g_pooled[t] = 0.f;
}

__global__ void pool_k(const int* __restrict__ batch_idx) {
    int t = blockIdx.x * blockDim.x + threadIdx.x;    // over G*32
    if (t >= G_NODES * 32) return;
    int node = t >> 5, c = t & 31;                    // ground nodes == first G
    float2 v = ((const float2*)(g_h + (size_t)node * H))[c];
    int b = batch_idx[node];
    atomicAdd(&g_pooled[b * H + 2 * c],     v.x);
    atomicAdd(&g_pooled[b * H + 2 * c + 1], v.y);
}

__global__ void final_k(const float* __restrict__ ow, const float* __restrict__ ob,
                        float* __restrict__ out) {
    int g = threadIdx.x;
    if (g < NG) {
        float acc = ob[0];
#pragma unroll
        for (int c = 0; c < H; c++) acc = fmaf(g_pooled[g * H + c], ow[c], acc);
        out[g] = acc;
    }
}

// ---------------- launch ----------------
extern "C" void kernel_launch(void* const* d_in, const int* in_sizes, int n_in,
                              void* d_out, int out_size) {
    const float* x      = (const float*)d_in[0];
    const int*   e_edge = (const int*)d_in[1];   // edge_index
    const int*   e_sub  = (const int*)d_in[2];   // subgraph_edge_index
    const int*   e_ns   = (const int*)d_in[3];   // node_subnode_index
    const int*   e_sn   = (const int*)d_in[4];   // subnode_node_index
    // d_in[5] ground_node (== i < G, recomputed), d_in[6] subgraph_batch_index (unused)
    const int*   batch  = (const int*)d_in[7];
    const float* emb_w  = (const float*)d_in[8];
    const float* emb_b  = (const float*)d_in[9];
    const float* wl     = (const float*)d_in[10];
    const float* bl     = (const float*)d_in[11];
    const float* wr     = (const float*)d_in[12];
    const float* ln_g   = (const float*)d_in[13];
    const float* ln_b   = (const float*)d_in[14];
    const float* out_w  = (const float*)d_in[15];
    const float* out_b  = (const float*)d_in[16];
    float* out = (float*)d_out;

    // reference eis order: edge_index, node_subnode, subgraph_edge, subnode_node
    const int* eis[4] = { e_edge, e_ns, e_sub, e_sn };

    const int TPB = 256;
    embed_k<<<(N_NODES * 32 + TPB - 1) / TPB, TPB>>>(x, emb_w, emb_b);

    for (int j = 0; j < 4; j++) {
        const int* ei = eis[j];
        reset_k<<<(N_NODES + TPB - 1) / TPB, TPB>>>();
        hist_k<<<(NE + TPB - 1) / TPB, TPB>>>(ei);
        alloc_k<<<(N_NODES + TPB - 1) / TPB, TPB>>>();
        fill_k<<<(NE + TPB - 1) / TPB, TPB>>>(ei);
        boff_k<<<1, 32>>>();
        bscatter_k<<<(N_NODES + TPB - 1) / TPB, TPB>>>();
        aggregate_k<<<(N_NODES * 32 + TPB - 1) / TPB, TPB>>>();
        transform_k<<<MAXT, TILE>>>(wl, bl, wr, j, (j < 3) ? 1 : 0);
    }

    ln_k<<<(N_NODES * 32 + TPB - 1) / TPB, TPB>>>(ln_g, ln_b);
    zero_pooled_k<<<(NG * H + TPB - 1) / TPB, TPB>>>();
    pool_k<<<(G_NODES * 32 + TPB - 1) / TPB, TPB>>>(batch);
    final_k<<<1, 128>>>(out_w, out_b, out);
}

// round 17
// speedup vs baseline: 1.4386x; 1.4386x over previous
#include <cuda_runtime.h>

#define N_NODES 100000
#define G_NODES 50000
#define NE      800000
#define H       64
#define FIN     32
#define NG      128
#define NC      4
#define TILE    96
#define MAXT    1064
#define LN_EPS  1e-5f

// ---------------- device scratch (allowed: __device__ globals) ----------------
__device__ float g_h[(size_t)N_NODES * H];
__device__ float g_h0[(size_t)N_NODES * H];
__device__ float g_hsum[(size_t)N_NODES * H];
__device__ int   g_deg[NC * N_NODES];
__device__ int   g_rowstart[NC * N_NODES];
__device__ int   g_cursor[NC * N_NODES];
__device__ int   g_csr_src[(size_t)NC * NE];
__device__ int   g_alloc[NC];
__device__ int   g_bcnt[NC * 21];
__device__ int   g_bcur[NC * 21];
__device__ int   g_boff[NC * 22];
__device__ int   g_toff[NC * 22];
__device__ int   g_sorted[NC * N_NODES];
__device__ float g_pooled[NG * H];

// ---------------- helpers ----------------
__device__ __forceinline__ unsigned long long fma2(unsigned long long a,
                                                   unsigned long long b,
                                                   unsigned long long c) {
    unsigned long long d;
    asm("fma.rn.f32x2 %0, %1, %2, %3;" : "=l"(d) : "l"(a), "l"(b), "l"(c));
    return d;
}

__device__ __forceinline__ unsigned long long pack2(float v) {
    union { float2 f; unsigned long long u; } p;
    p.f.x = v; p.f.y = v;
    return p.u;
}

// ---------------- embedding: h = x @ emb_w + emb_b ; h0 = h ----------------
__global__ void embed_k(const float* __restrict__ x,
                        const float* __restrict__ w,
                        const float* __restrict__ b) {
    __shared__ float sw[FIN * H];
    __shared__ float sb[H];
    for (int i = threadIdx.x; i < FIN * H; i += blockDim.x) sw[i] = w[i];
    if (threadIdx.x < H) sb[threadIdx.x] = b[threadIdx.x];
    __syncthreads();
    int t = blockIdx.x * blockDim.x + threadIdx.x;  // over N*32
    if (t >= N_NODES * 32) return;
    int node = t >> 5, c = t & 31;
    const float* xr = x + node * FIN;
    float a0 = sb[c], a1 = sb[c + 32];
#pragma unroll
    for (int f = 0; f < FIN; f++) {
        float xv = xr[f];
        a0 = fmaf(xv, sw[f * H + c], a0);
        a1 = fmaf(xv, sw[f * H + c + 32], a1);
    }
    size_t base = (size_t)node * H;
    g_h[base + c] = a0;  g_h[base + c + 32] = a1;
    g_h0[base + c] = a0; g_h0[base + c + 32] = a1;
}

// ---------------- batched CSR / bucket build (all 4 convs at once) ----------------
__global__ void reset4_k() {
    int t = blockIdx.x * blockDim.x + threadIdx.x;
    if (t < NC * N_NODES) g_deg[t] = 0;
    if (t < NC) g_alloc[t] = 0;
    if (t < NC * 21) { g_bcnt[t] = 0; g_bcur[t] = 0; }
    if (t < NG * H) g_pooled[t] = 0.f;
}

__global__ void hist4_k(const int* __restrict__ e0, const int* __restrict__ e1,
                        const int* __restrict__ e2, const int* __restrict__ e3) {
    int j = blockIdx.y;
    const int* ei = (j == 0) ? e0 : (j == 1) ? e1 : (j == 2) ? e2 : e3;
    int e = blockIdx.x * blockDim.x + threadIdx.x;
    if (e >= NE) return;
    int dst = ei[NE + e];
    if (j == 3 && dst >= G_NODES) return;   // conv3 output only needed on ground nodes
    atomicAdd(&g_deg[j * N_NODES + dst], 1);
}

// block-scan allocation: one global atomic per block instead of per node
__global__ void alloc_scan4_k() {
    __shared__ int s_scan[256];
    __shared__ int s_base;
    __shared__ int s_bc[21];
    int j = blockIdx.y;
    int tid = threadIdx.x;
    int i = blockIdx.x * 256 + tid;
    if (tid < 21) s_bc[tid] = 0;
    int d = (i < N_NODES) ? g_deg[j * N_NODES + i] : 0;
    s_scan[tid] = d;
    __syncthreads();
#pragma unroll
    for (int off = 1; off < 256; off <<= 1) {
        int v = (tid >= off) ? s_scan[tid - off] : 0;
        __syncthreads();
        s_scan[tid] += v;
        __syncthreads();
    }
    if (tid == 255) s_base = atomicAdd(&g_alloc[j], s_scan[255]);
    if (i < N_NODES && (j != 3 || i < G_NODES)) {
        int bkt = d < 20 ? d : 20;
        atomicAdd(&s_bc[bkt], 1);
    }
    __syncthreads();
    if (i < N_NODES) {
        int rs = s_base + s_scan[tid] - d;   // exclusive prefix + block base
        g_rowstart[j * N_NODES + i] = rs;
        g_cursor[j * N_NODES + i]   = rs;
    }
    if (tid < 21 && s_bc[tid] > 0) atomicAdd(&g_bcnt[j * 21 + tid], s_bc[tid]);
}

__global__ void fill4_k(const int* __restrict__ e0, const int* __restrict__ e1,
                        const int* __restrict__ e2, const int* __restrict__ e3) {
    int j = blockIdx.y;
    const int* ei = (j == 0) ? e0 : (j == 1) ? e1 : (j == 2) ? e2 : e3;
    int e = blockIdx.x * blockDim.x + threadIdx.x;
    if (e >= NE) return;
    int dst = ei[NE + e];
    if (j == 3 && dst >= G_NODES) return;
    int pos = atomicAdd(&g_cursor[j * N_NODES + dst], 1);
    g_csr_src[(size_t)j * NE + pos] = ei[e];
}

__global__ void boff4_k() {
    int j = threadIdx.x;
    if (j < NC) {
        int off = 0, t = 0;
#pragma unroll 1
        for (int q = 0; q < 21; q++) {
            g_boff[j * 22 + q] = off;
            g_toff[j * 22 + q] = t;
            int c = g_bcnt[j * 21 + q];
            off += c;
            t += (c + TILE - 1) / TILE;
        }
        g_boff[j * 22 + 21] = off;
        g_toff[j * 22 + 21] = t;
    }
}

__global__ void bscatter4_k() {
    __shared__ int s_cnt[21], s_base[21];
    int j = blockIdx.y;
    int tid = threadIdx.x;
    int i = blockIdx.x * 256 + tid;
    if (tid < 21) s_cnt[tid] = 0;
    __syncthreads();
    int bkt = 0, lr = 0;
    bool act = (i < N_NODES) && (j != 3 || i < G_NODES);
    if (act) {
        int d = g_deg[j * N_NODES + i];
        bkt = d < 20 ? d : 20;
        lr = atomicAdd(&s_cnt[bkt], 1);
    }
    __syncthreads();
    if (tid < 21 && s_cnt[tid] > 0)
        s_base[tid] = atomicAdd(&g_bcur[j * 21 + tid], s_cnt[tid]);
    __syncthreads();
    if (act)
        g_sorted[j * N_NODES + g_boff[j * 22 + bkt] + s_base[bkt] + lr] = i;
}

// ---------------- aggregation: hsum[i] = sum_{e: dst==i} h[src_e] ----------------
__global__ void aggregate_k(int j, int nmax) {
    int gt = blockIdx.x * blockDim.x + threadIdx.x;   // warp per node
    int node = gt >> 5;
    if (node >= nmax) return;
    int lane = gt & 31;
    int start = g_rowstart[j * N_NODES + node];
    int d = g_deg[j * N_NODES + node];
    const int* csr = g_csr_src + (size_t)j * NE;
    const float2* hp = (const float2*)g_h;
    float2 acc = make_float2(0.f, 0.f);
    int e = 0;
    for (; e + 4 <= d; e += 4) {
        int s0 = csr[start + e];
        int s1 = csr[start + e + 1];
        int s2 = csr[start + e + 2];
        int s3 = csr[start + e + 3];
        float2 v0 = hp[(size_t)s0 * 32 + lane];
        float2 v1 = hp[(size_t)s1 * 32 + lane];
        float2 v2 = hp[(size_t)s2 * 32 + lane];
        float2 v3 = hp[(size_t)s3 * 32 + lane];
        acc.x += v0.x + v1.x + v2.x + v3.x;
        acc.y += v0.y + v1.y + v2.y + v3.y;
    }
    for (; e < d; e++) {
        int s = csr[start + e];
        float2 v = hp[(size_t)s * 32 + lane];
        acc.x += v.x; acc.y += v.y;
    }
    ((float2*)g_hsum)[(size_t)node * 32 + lane] = acc;
}

// ---------------- bucketed linear: h = epilogue(hsum@wl[k] + bl[k] + h@wr[k]) ----------------
__device__ __forceinline__ void stage_rows(const float* __restrict__ base,
                                           int node, int lane, int warp,
                                           float* __restrict__ s_row) {
#pragma unroll 1
    for (int r = 0; r < 32; r++) {
        int nd = __shfl_sync(0xffffffffu, node, r);
        float2 v = ((const float2*)(base + (size_t)nd * H))[lane];
        int row = warp * 32 + r;
        s_row[row * 65 + 2 * lane]     = v.x;
        s_row[row * 65 + 2 * lane + 1] = v.y;
    }
    __syncwarp();
}

__device__ __forceinline__ void compute_phase(const float* __restrict__ s_w,
                                              const float* __restrict__ myrow,
                                              unsigned long long* acc) {
#pragma unroll 4
    for (int f = 0; f < H; f++) {
        unsigned long long ss = pack2(myrow[f]);
        const ulonglong2* wf = (const ulonglong2*)(s_w + f * H);
#pragma unroll
        for (int q = 0; q < 16; q++) {
            ulonglong2 wv = wf[q];
            acc[2 * q]     = fma2(ss, wv.x, acc[2 * q]);
            acc[2 * q + 1] = fma2(ss, wv.y, acc[2 * q + 1]);
        }
    }
}

// LN + residual + pooled atomics over the register-resident 64-vector
__device__ __forceinline__ void ln_pool_epilogue(const float* v2,  // 32 float2 as floats
                                                 int node,
                                                 const float* __restrict__ s_lng,
                                                 const float* __restrict__ s_lnb,
                                                 const int* __restrict__ batch_idx) {
    const float2* v = (const float2*)v2;
    float mu = 0.f;
#pragma unroll
    for (int p = 0; p < 32; p++) { mu += v[p].x + v[p].y; }
    mu *= (1.f / H);
    float var = 0.f;
#pragma unroll
    for (int p = 0; p < 32; p++) {
        float dx = v[p].x - mu, dy = v[p].y - mu;
        var += dx * dx + dy * dy;
    }
    float rs = rsqrtf(var * (1.f / H) + LN_EPS);
    int b = batch_idx[node];
    const float2* h0p = (const float2*)(g_h0 + (size_t)node * H);
    float* pooled = g_pooled + b * H;
#pragma unroll
    for (int p = 0; p < 32; p++) {
        float2 h0v = h0p[p];
        float ox = (v[p].x - mu) * rs * s_lng[2 * p]     + s_lnb[2 * p]     + h0v.x;
        float oy = (v[p].y - mu) * rs * s_lng[2 * p + 1] + s_lnb[2 * p + 1] + h0v.y;
        atomicAdd(&pooled[2 * p],     ox);
        atomicAdd(&pooled[2 * p + 1], oy);
    }
}

__global__ __launch_bounds__(TILE) void transform_k(const float* __restrict__ wl_all,
                                                    const float* __restrict__ bl_all,
                                                    const float* __restrict__ wr_all,
                                                    const float* __restrict__ ln_g,
                                                    const float* __restrict__ ln_b,
                                                    const int* __restrict__ batch_idx,
                                                    int jconv, int mode) {  // mode 0: relu+store, 1: ln+pool
    __shared__ float s_w[H * H];
    __shared__ float s_bl[H];
    __shared__ float s_lng[H], s_lnb[H];
    __shared__ float s_row[TILE * 65];
    __shared__ int s_meta[3];

    int tid = threadIdx.x;
    if (tid == 0) {
        int t = blockIdx.x;
        int k = -1, pos0 = 0, cnt = 0;
        const int* toff = g_toff + jconv * 22;
        const int* boff = g_boff + jconv * 22;
        if (t < toff[21]) {
#pragma unroll 1
            for (int q = 0; q < 21; q++) {
                if (t < toff[q + 1]) { k = q; break; }
            }
            pos0 = boff[k] + (t - toff[k]) * TILE;
            int rem = boff[k + 1] - pos0;
            cnt = rem < TILE ? rem : TILE;
        }
        s_meta[0] = k; s_meta[1] = pos0; s_meta[2] = cnt;
    }
    if (mode == 1 && tid < H) { s_lng[tid] = ln_g[tid]; s_lnb[tid] = ln_b[tid]; }
    __syncthreads();
    int k = s_meta[0];
    if (k < 0) return;                       // block-uniform
    int pos0 = s_meta[1], cnt = s_meta[2];
    int ii = tid < cnt ? tid : cnt - 1;      // clamp for full-warp participation
    int node = g_sorted[jconv * N_NODES + pos0 + ii];

    if (k == 0) {                            // deg==0: h unchanged
        if (tid < cnt) {
            if (mode == 0) {
                float4* hp = (float4*)(g_h + (size_t)node * H);
#pragma unroll
                for (int q = 0; q < 16; q++) {
                    float4 v = hp[q];
                    v.x = fmaxf(v.x, 0.f); v.y = fmaxf(v.y, 0.f);
                    v.z = fmaxf(v.z, 0.f); v.w = fmaxf(v.w, 0.f);
                    hp[q] = v;
                }
            } else {
                float buf[H];
                const float4* hp = (const float4*)(g_h + (size_t)node * H);
#pragma unroll
                for (int q = 0; q < 16; q++) ((float4*)buf)[q] = hp[q];
                ln_pool_epilogue(buf, node, s_lng, s_lnb, batch_idx);
            }
        }
        return;                              // block-uniform
    }

    const float* wl = wl_all + (size_t)(jconv * 21 + k) * H * H;
    const float* wr = wr_all + (size_t)(jconv * 21 + k) * H * H;
    const float* bl = bl_all + (size_t)(jconv * 21 + k) * H;

    {
        const float4* src = (const float4*)wl;
        float4* dst4 = (float4*)s_w;
        for (int i = tid; i < H * H / 4; i += TILE) dst4[i] = src[i];
        if (tid < H) s_bl[tid] = bl[tid];
    }
    __syncthreads();

    int lane = tid & 31, warp = tid >> 5;
    unsigned long long acc[32];              // acc[p] = channels (2p, 2p+1)
#pragma unroll
    for (int p = 0; p < 32; p++) acc[p] = ((const unsigned long long*)s_bl)[p];

    stage_rows(g_hsum, node, lane, warp, s_row);
    compute_phase(s_w, s_row + tid * 65, acc);

    __syncthreads();   // everyone done with wl
    {
        const float4* src = (const float4*)wr;
        float4* dst4 = (float4*)s_w;
        for (int i = tid; i < H * H / 4; i += TILE) dst4[i] = src[i];
    }
    __syncthreads();

    stage_rows(g_h, node, lane, warp, s_row);
    compute_phase(s_w, s_row + tid * 65, acc);

    if (tid < cnt) {
        if (mode == 0) {
            float2* outp = (float2*)(g_h + (size_t)node * H);
#pragma unroll
            for (int p = 0; p < 32; p++) {
                float2 v = *(float2*)&acc[p];
                v.x = fmaxf(v.x, 0.f); v.y = fmaxf(v.y, 0.f);
                outp[p] = v;
            }
        } else {
            ln_pool_epilogue((const float*)acc, node, s_lng, s_lnb, batch_idx);
        }
    }
}

// ---------------- final projection ----------------
__global__ void final_k(const float* __restrict__ ow, const float* __restrict__ ob,
                        float* __restrict__ out) {
    int g = threadIdx.x;
    if (g < NG) {
        float acc = ob[0];
#pragma unroll
        for (int c = 0; c < H; c++) acc = fmaf(g_pooled[g * H + c], ow[c], acc);
        out[g] = acc;
    }
}

// ---------------- launch ----------------
extern "C" void kernel_launch(void* const* d_in, const int* in_sizes, int n_in,
                              void* d_out, int out_size) {
    const float* x      = (const float*)d_in[0];
    const int*   e_edge = (const int*)d_in[1];   // edge_index
    const int*   e_sub  = (const int*)d_in[2];   // subgraph_edge_index
    const int*   e_ns   = (const int*)d_in[3];   // node_subnode_index
    const int*   e_sn   = (const int*)d_in[4];   // subnode_node_index
    // d_in[5] ground_node (== i < G, recomputed), d_in[6] subgraph_batch_index (unused)
    const int*   batch  = (const int*)d_in[7];
    const float* emb_w  = (const float*)d_in[8];
    const float* emb_b  = (const float*)d_in[9];
    const float* wl     = (const float*)d_in[10];
    const float* bl     = (const float*)d_in[11];
    const float* wr     = (const float*)d_in[12];
    const float* ln_g   = (const float*)d_in[13];
    const float* ln_b   = (const float*)d_in[14];
    const float* out_w  = (const float*)d_in[15];
    const float* out_b  = (const float*)d_in[16];
    float* out = (float*)d_out;

    const int TPB = 256;

    // reference eis order: edge_index, node_subnode, subgraph_edge, subnode_node
    // conv0=e_edge, conv1=e_ns, conv2=e_sub, conv3=e_sn

    // ---- batched CSR + bucket build for all 4 convs (independent of h) ----
    reset4_k<<<(NC * N_NODES + TPB - 1) / TPB, TPB>>>();
    {
        dim3 gE((NE + TPB - 1) / TPB, NC);
        dim3 gN((N_NODES + TPB - 1) / TPB, NC);
        hist4_k<<<gE, TPB>>>(e_edge, e_ns, e_sub, e_sn);
        alloc_scan4_k<<<gN, 256>>>();
        boff4_k<<<1, 32>>>();
        bscatter4_k<<<gN, 256>>>();
        fill4_k<<<gE, TPB>>>(e_edge, e_ns, e_sub, e_sn);
    }

    embed_k<<<(N_NODES * 32 + TPB - 1) / TPB, TPB>>>(x, emb_w, emb_b);

    for (int j = 0; j < 4; j++) {
        int nmax = (j == 3) ? G_NODES : N_NODES;
        aggregate_k<<<(nmax * 32 + TPB - 1) / TPB, TPB>>>(j, nmax);
        transform_k<<<MAXT, TILE>>>(wl, bl, wr, ln_g, ln_b, batch, j,
                                    (j < 3) ? 0 : 1);
    }

    final_k<<<1, 128>>>(out_w, out_b, out);
}